// round 13
// baseline (speedup 1.0000x reference)
#include <cuda_runtime.h>
#include <cstdint>
#include <cstddef>
#include <math.h>

// ---------------------------------------------------------------------------
// Scratch (device globals -- no allocation allowed)
// ---------------------------------------------------------------------------
__device__ int   g_knn1[2 * 4096 * 16];
__device__ int   g_knn2[2 * 2048 * 16];
__device__ float g_part[4194304];          // split-K partials (16MB)
__device__ uint4 g_W1p[32768];             // W1 bf16 h/m fragment-permuted
__device__ uint4 g_W2p[65536];             // W2 bf16 h/m fragment-permuted
__device__ uint4 g_chp[262144];            // ch  packed bf16 h/m pairs (4MB)
__device__ uint4 g_ch1p[262144];           // ch1 packed bf16 h/m pairs (4MB)

// ---------------------------------------------------------------------------
// helpers
// ---------------------------------------------------------------------------
__device__ __forceinline__ unsigned int pack_bf16(float a, float b) {
    unsigned int r;
    asm("cvt.rn.bf16x2.f32 %0, %1, %2;" : "=r"(r) : "f"(b), "f"(a));
    return r;
}
__device__ __forceinline__ void split_pair(float v0, float v1,
                                           unsigned int& hp, unsigned int& mp) {
    hp = pack_bf16(v0, v1);
    float h0 = __uint_as_float(hp << 16);
    float h1 = __uint_as_float(hp & 0xffff0000u);
    mp = pack_bf16(v0 - h0, v1 - h1);
}
__device__ __forceinline__ void mma_bf16(float c[4], const unsigned int a[4],
                                         unsigned int b0, unsigned int b1) {
    asm("mma.sync.aligned.m16n8k16.row.col.f32.bf16.bf16.f32 "
        "{%0,%1,%2,%3}, {%4,%5,%6,%7}, {%8,%9}, {%0,%1,%2,%3};"
        : "+f"(c[0]), "+f"(c[1]), "+f"(c[2]), "+f"(c[3])
        : "r"(a[0]), "r"(a[1]), "r"(a[2]), "r"(a[3]), "r"(b0), "r"(b1));
}
__device__ __forceinline__ unsigned long long pack2(float x, float y) {
    unsigned long long r;
    asm("mov.b64 %0, {%1, %2};" : "=l"(r) : "f"(x), "f"(y));
    return r;
}
__device__ __forceinline__ unsigned long long add2(unsigned long long a,
                                                   unsigned long long b) {
    unsigned long long r;
    asm("add.rn.f32x2 %0, %1, %2;" : "=l"(r) : "l"(a), "l"(b));
    return r;
}
__device__ __forceinline__ unsigned long long mul2(unsigned long long a,
                                                   unsigned long long b) {
    unsigned long long r;
    asm("mul.rn.f32x2 %0, %1, %2;" : "=l"(r) : "l"(a), "l"(b));
    return r;
}
__device__ __forceinline__ void cp_async8(unsigned int dst, const void* src) {
    asm volatile("cp.async.ca.shared.global [%0], [%1], 8;"
                 :: "r"(dst), "l"(src));
}
__device__ __forceinline__ void cp_async16(unsigned int dst, const void* src) {
    asm volatile("cp.async.cg.shared.global [%0], [%1], 16;"
                 :: "r"(dst), "l"(src));
}
__device__ __forceinline__ void mbar_init(unsigned int addr, unsigned int cnt) {
    asm volatile("mbarrier.init.shared::cta.b64 [%0], %1;"
                 :: "r"(addr), "r"(cnt) : "memory");
}
__device__ __forceinline__ void mbar_arrive(unsigned int addr) {
    asm volatile("mbarrier.arrive.shared::cta.b64 _, [%0];"
                 :: "r"(addr) : "memory");
}
__device__ __forceinline__ void cpasync_arrive_noinc(unsigned int addr) {
    asm volatile("cp.async.mbarrier.arrive.noinc.shared::cta.b64 [%0];"
                 :: "r"(addr) : "memory");
}
__device__ __forceinline__ void mbar_wait_acq(unsigned int addr,
                                              unsigned int phase) {
    asm volatile(
        "{\n\t"
        ".reg .pred P1;\n\t"
        "WAIT_LOOP_%=:\n\t"
        "mbarrier.try_wait.parity.acquire.cta.shared::cta.b64 P1, [%0], %1, 0x989680;\n\t"
        "@P1 bra WAIT_DONE_%=;\n\t"
        "bra WAIT_LOOP_%=;\n\t"
        "WAIT_DONE_%=:\n\t"
        "}"
        :: "r"(addr), "r"(phase) : "memory");
}
__device__ __forceinline__ void mbar_wait_rlx(unsigned int addr,
                                              unsigned int phase) {
    asm volatile(
        "{\n\t"
        ".reg .pred P1;\n\t"
        "WAIT_LOOP_%=:\n\t"
        "mbarrier.try_wait.parity.relaxed.cta.shared::cta.b64 P1, [%0], %1, 0x989680;\n\t"
        "@P1 bra WAIT_DONE_%=;\n\t"
        "bra WAIT_LOOP_%=;\n\t"
        "WAIT_DONE_%=:\n\t"
        "}"
        :: "r"(addr), "r"(phase) : "memory");
}

// ---------------------------------------------------------------------------
// prep: one kernel, block-range dispatch:
//  blocks [0,1024)    : KNN stage 1
//  blocks [1024,1536) : KNN stage 2
//  blocks [1536,2992) : W1/W2 bf16 fragment-permute, ch split, pos copy
// KNN: warp-per-center, negated-SoA smem tiles, packed f32x2 distance math
// (rounds exactly like scalar rn ops). Lanes 0..15 hold sorted top-16 u64
// keys ((dist_bits<<32)|idx); reproduces jax.lax.top_k(-d2) ordering exactly.
// Inner loop reads 4 points/lane via LDS.128; ballots remain PER-DISTANCE
// (R9 insert semantics -- the R10 min-gate regression is avoided).
// ---------------------------------------------------------------------------
__global__ void __launch_bounds__(256) prep_kernel(
    const float* __restrict__ pos, int* __restrict__ knn1,
    int* __restrict__ knn2,
    const float* __restrict__ W1, const float* __restrict__ W2,
    const float* __restrict__ ch, float* __restrict__ out)
{
    constexpr int TILE = 1024;
    __shared__ __align__(16) float sn[3 * TILE];   // -x @0, -y @1024, -z @2048

    const int tid = threadIdx.x;

    if (blockIdx.x >= 1536) {
        int i = (blockIdx.x - 1536) * 256 + tid;
        if (i < 32768) {                               // W1p
            int p = i >> 9, n = (i >> 2) & 127, t = i & 3;
            int k0 = 16 * p + 2 * t;
            float v0 = __ldg(W1 + n * 1024 + k0);
            float v1 = __ldg(W1 + n * 1024 + k0 + 1);
            float v2 = __ldg(W1 + n * 1024 + k0 + 8);
            float v3 = __ldg(W1 + n * 1024 + k0 + 9);
            uint4 o;
            split_pair(v0, v1, o.x, o.z);
            split_pair(v2, v3, o.y, o.w);
            g_W1p[i] = o;
        } else if (i < 98304) {                        // W2p
            int j = i - 32768;
            int p = j >> 9, n = (j >> 2) & 127, t = j & 3;
            int k0 = 16 * p + 2 * t;
            float v0 = __ldg(W2 + n * 2048 + k0);
            float v1 = __ldg(W2 + n * 2048 + k0 + 1);
            float v2 = __ldg(W2 + n * 2048 + k0 + 8);
            float v3 = __ldg(W2 + n * 2048 + k0 + 9);
            uint4 o;
            split_pair(v0, v1, o.x, o.z);
            split_pair(v2, v3, o.y, o.w);
            g_W2p[j] = o;
        } else if (i < 360448) {                       // chp (4 floats/thr)
            int j = i - 98304;
            float4 v = __ldg((const float4*)ch + j);
            uint4 o;
            split_pair(v.x, v.y, o.x, o.y);
            split_pair(v.z, v.w, o.z, o.w);
            g_chp[j] = o;
        } else if (i < 372736) {                       // pos copy
            int j = i - 360448;
            int b = j / 6144;
            int rem = j - b * 6144;
            int n = rem / 3;
            int d = rem - n * 3;
            out[j] = pos[((size_t)b * 8192 + 4 * n) * 3 + d];
        }
        return;
    }

    // -------------------- KNN region --------------------
    const int warp = tid >> 5;
    const int lane = tid & 31;

    int pstride, n_in, n_out, center;
    int* outp;
    if (blockIdx.x < 1024) {
        pstride = 1; n_in = 8192; n_out = 4096; outp = knn1;
        center = blockIdx.x * 8 + warp;
    } else {
        pstride = 2; n_in = 4096; n_out = 2048; outp = knn2;
        center = (blockIdx.x - 1024) * 8 + warp;
    }
    const int b = center / n_out;
    const int n = center % n_out;

    const float* posb = pos + (size_t)b * 8192 * 3;
    const float cx = posb[(size_t)(n * 2 * pstride) * 3 + 0];
    const float cy = posb[(size_t)(n * 2 * pstride) * 3 + 1];
    const float cz = posb[(size_t)(n * 2 * pstride) * 3 + 2];
    const unsigned long long cxx = pack2(cx, cx);
    const unsigned long long cyy = pack2(cy, cy);
    const unsigned long long czz = pack2(cz, cz);

    unsigned long long lkey   = 0x7F800000FFFFFFFFull;
    unsigned long long thresh = 0x7F800000FFFFFFFFull;
    float tf = __int_as_float(0x7F800000);

    const int nTiles = n_in / TILE;
    float v[12];

#pragma unroll
    for (int k = 0; k < 4; k++) {
        int p = k * 256 + tid;
#pragma unroll
        for (int d = 0; d < 3; d++)
            v[3 * k + d] = __ldg(posb + (size_t)p * pstride * 3 + d);
    }

    for (int t = 0; t < nTiles; t++) {
#pragma unroll
        for (int k = 0; k < 4; k++) {
            int p = k * 256 + tid;
            sn[p]        = -v[3 * k];
            sn[p + 1024] = -v[3 * k + 1];
            sn[p + 2048] = -v[3 * k + 2];
        }
        __syncthreads();
        if (t + 1 < nTiles) {
            const int base = (t + 1) * TILE;
#pragma unroll
            for (int k = 0; k < 4; k++) {
                int p = base + k * 256 + tid;
#pragma unroll
                for (int d = 0; d < 3; d++)
                    v[3 * k + d] = __ldg(posb + (size_t)p * pstride * 3 + d);
            }
        }

        const int jbase = t * TILE;
#pragma unroll 2
        for (int it = 0; it < 8; ++it) {       // 128 points per iteration
            const int j = it * 128 + 4 * lane;
            ulonglong2 X = *(const ulonglong2*)(sn + j);
            ulonglong2 Y = *(const ulonglong2*)(sn + 1024 + j);
            ulonglong2 Z = *(const ulonglong2*)(sn + 2048 + j);
            unsigned long long ax0 = add2(cxx, X.x), ax1 = add2(cxx, X.y);
            unsigned long long ay0 = add2(cyy, Y.x), ay1 = add2(cyy, Y.y);
            unsigned long long az0 = add2(czz, Z.x), az1 = add2(czz, Z.y);
            unsigned long long d01 =
                add2(add2(mul2(ax0, ax0), mul2(ay0, ay0)), mul2(az0, az0));
            unsigned long long d23 =
                add2(add2(mul2(ax1, ax1), mul2(ay1, ay1)), mul2(az1, az1));
            float dd[4];
            asm("mov.b64 {%0, %1}, %2;" : "=f"(dd[0]), "=f"(dd[1]) : "l"(d01));
            asm("mov.b64 {%0, %1}, %2;" : "=f"(dd[2]), "=f"(dd[3]) : "l"(d23));
#pragma unroll
            for (int h = 0; h < 4; h++) {
                float dv = dd[h];
                unsigned mask = __ballot_sync(0xffffffffu, dv <= tf);
                while (mask) {
                    const int src = __ffs(mask) - 1;
                    mask &= mask - 1;
                    float cd = __shfl_sync(0xffffffffu, dv, src);
                    unsigned idx = (unsigned)(jbase + it * 128 + 4 * src + h);
                    unsigned long long ck =
                        ((unsigned long long)__float_as_uint(cd) << 32) | idx;
                    if (ck < thresh) {   // uniform
                        unsigned long long up =
                            __shfl_up_sync(0xffffffffu, lkey, 1);
                        bool keep = (lkey < ck);
                        unsigned long long ins =
                            (lane == 0 || up < ck) ? ck : up;
                        lkey = keep ? lkey : ins;
                        thresh = __shfl_sync(0xffffffffu, lkey, 15);
                        tf = __uint_as_float((unsigned)(thresh >> 32));
                    }
                }
            }
        }
        __syncthreads();
    }

    if (lane < 16)
        outp[(size_t)center * 16 + lane] =
            (int)(unsigned)(lkey & 0xffffffffull);
}

// ---------------------------------------------------------------------------
// Gathered-conv GEMM, 3xBF16 (h+m split) m16n8k16 tensor cores.
// 6-stage mbarrier producer/consumer ring, lookahead 3 (skew tolerance 3
// iterations, NO block barrier in the mainloop). full[s]: 256 arrivals via
// cp.async.mbarrier.arrive.noinc; empty[s]: 256 thread arrivals after the
// stage's last LDS. knn indices preloaded & packed (13b each).
// ---------------------------------------------------------------------------
template <int CIN, int NSPLIT>
__global__ void __launch_bounds__(256, 2)
gconv_mma(const uint2* __restrict__ chp, const int* __restrict__ knn,
          const uint4* __restrict__ Wp, float* __restrict__ part,
          int n_in, int n_out, int Mtot)
{
    constexpr int BM = 128, BN = 128, BK = 16, S2 = 132, STAGES = 6;
    constexpr int ABYTES = 8 * S2 * 8;               // 8448 B per A stage
    constexpr int BBYTES = 512 * 16;                 // 8192 B per B stage
    constexpr int BOFF   = STAGES * ABYTES;          // 50688
    constexpr int MBOFF  = BOFF + STAGES * BBYTES;   // 99840
    constexpr int NPB = 16 / NSPLIT;
    constexpr int ITERS = NPB * CIN / BK;
    constexpr int CIN2 = CIN / 2;
    extern __shared__ __align__(16) unsigned char dynraw[];

    const unsigned int smem0 =
        (unsigned int)__cvta_generic_to_shared(dynraw);
    const int tid = threadIdx.x;
    const int split = blockIdx.y;
    const int m_base = blockIdx.x * BM;
    const int b = m_base / n_out;
    const int warp = tid >> 5, lane = tid & 31;
    const int g = lane >> 2, t = lane & 3;
    const int wm = (warp & 3) * 32, wn = (warp >> 2) * 64;

    if (tid == 0) {
#pragma unroll
        for (int s = 0; s < STAGES; s++) {
            mbar_init(smem0 + MBOFF + s * 8, 256);        // full
            mbar_init(smem0 + MBOFF + 48 + s * 8, 256);   // empty
        }
    }
    __syncthreads();

    const int arow = tid >> 1;
    const int ahalf = (tid & 1) * 4;
    const uint2* chb = chp + (size_t)b * n_in * CIN2;
    const int kpan0 = (split * NPB * CIN) >> 4;

    // preload this row's neighbor indices for this split, pack 13b each
    unsigned long long jpack;
    {
        const int* base = knn + ((size_t)(m_base + arow) * 16) + split * NPB;
        if (NPB == 4) {
            int4 j4 = *(const int4*)base;
            jpack = (unsigned long long)(unsigned)j4.x
                  | ((unsigned long long)(unsigned)j4.y << 13)
                  | ((unsigned long long)(unsigned)j4.z << 26)
                  | ((unsigned long long)(unsigned)j4.w << 39);
        } else {
            int2 j2 = *(const int2*)base;
            jpack = (unsigned long long)(unsigned)j2.x
                  | ((unsigned long long)(unsigned)j2.y << 13);
        }
    }

    const unsigned int abase = smem0 + (ahalf * S2 + arow) * 8;
    const unsigned int bbase = smem0 + BOFF + tid * 32;

    float acc[2][8][4];
#pragma unroll
    for (int i = 0; i < 2; i++)
#pragma unroll
        for (int j = 0; j < 8; j++)
#pragma unroll
            for (int k = 0; k < 4; k++) acc[i][j][k] = 0.0f;

    int ps = 0; unsigned int pp = 1;       // producer cursor (phase 1 first)
    int cs = 0; unsigned int cphase = 0;   // consumer cursor

    auto produce = [&](int it) {
        mbar_wait_rlx(smem0 + MBOFF + 48 + ps * 8, pp);
        const int kn = (it * BK) / CIN;
        const int j = (int)((jpack >> (kn * 13)) & 8191);
        const int c0 = ((it * BK) % CIN) >> 1;
        const uint2* srcA = chb + (size_t)j * CIN2 + c0 + ahalf;
        const unsigned int dA = abase + ps * ABYTES;
#pragma unroll
        for (int i = 0; i < 4; i++) cp_async8(dA + i * (S2 * 8), srcA + i);
        const uint4* srcB = Wp + ((size_t)(kpan0 + it) << 9) + tid * 2;
        const unsigned int dB = bbase + ps * BBYTES;
#pragma unroll
        for (int q = 0; q < 2; q++) cp_async16(dB + q * 16, srcB + q);
        cpasync_arrive_noinc(smem0 + MBOFF + ps * 8);
        if (++ps == STAGES) { ps = 0; pp ^= 1; }
    };

    produce(0); produce(1); produce(2);

    for (int it = 0; it < ITERS; ++it) {
        if (it + 3 < ITERS) produce(it + 3);

        mbar_wait_acq(smem0 + MBOFF + cs * 8, cphase);
        const uint2* As = (const uint2*)(dynraw + cs * ABYTES);
        const uint4* Bs = (const uint4*)(dynraw + BOFF + cs * BBYTES);

        unsigned int Ah[2][4], Am[2][4];
#pragma unroll
        for (int mt = 0; mt < 2; mt++) {
            const int r0 = wm + mt * 16 + g;
            uint2 a0 = As[t * S2 + r0];
            uint2 a1 = As[t * S2 + r0 + 8];
            uint2 a2 = As[(t + 4) * S2 + r0];
            uint2 a3 = As[(t + 4) * S2 + r0 + 8];
            Ah[mt][0] = a0.x; Am[mt][0] = a0.y;
            Ah[mt][1] = a1.x; Am[mt][1] = a1.y;
            Ah[mt][2] = a2.x; Am[mt][2] = a2.y;
            Ah[mt][3] = a3.x; Am[mt][3] = a3.y;
        }
#pragma unroll
        for (int nt = 0; nt < 8; nt++) {
            uint4 w = Bs[(wn + nt * 8 + g) * 4 + t];   // {bh0,bh1,bm0,bm1}
#pragma unroll
            for (int mt = 0; mt < 2; mt++) {
                mma_bf16(acc[mt][nt], Ah[mt], w.x, w.y);
                mma_bf16(acc[mt][nt], Ah[mt], w.z, w.w);
                mma_bf16(acc[mt][nt], Am[mt], w.x, w.y);
            }
        }

        mbar_arrive(smem0 + MBOFF + 48 + cs * 8);      // stage consumed
        if (++cs == STAGES) { cs = 0; cphase ^= 1; }
    }

    float* dst = part + ((size_t)split * Mtot + m_base) * BN;
#pragma unroll
    for (int mt = 0; mt < 2; mt++)
#pragma unroll
        for (int nt = 0; nt < 8; nt++) {
            const int r = wm + mt * 16 + g;
            const int c = wn + nt * 8 + 2 * t;
            *(float2*)(dst + (size_t)r * BN + c) =
                make_float2(acc[mt][nt][0], acc[mt][nt][1]);
            *(float2*)(dst + (size_t)(r + 8) * BN + c) =
                make_float2(acc[mt][nt][2], acc[mt][nt][3]);
        }
}

// ---------------------------------------------------------------------------
// combine (mid): sum partials + bias + LN + SiLU -> packed bf16 h/m pairs
// ---------------------------------------------------------------------------
template <int NSPLIT>
__global__ void __launch_bounds__(256) combine_mid(
    const float* __restrict__ part, int M,
    const float* __restrict__ bias, const float* __restrict__ gamma,
    const float* __restrict__ beta, uint4* __restrict__ outp)
{
    const int lane = threadIdx.x & 31;
    const int row = blockIdx.x * 8 + (threadIdx.x >> 5);

    const float4* p4 = (const float4*)part;
    float4 x = p4[(size_t)row * 32 + lane];
#pragma unroll
    for (int s = 1; s < NSPLIT; s++) {
        float4 y = p4[((size_t)s * M + row) * 32 + lane];
        x.x += y.x; x.y += y.y; x.z += y.z; x.w += y.w;
    }
    float4 bb = *(const float4*)(bias + lane * 4);
    float4 gg = *(const float4*)(gamma + lane * 4);
    float4 be = *(const float4*)(beta + lane * 4);
    x.x += bb.x; x.y += bb.y; x.z += bb.z; x.w += bb.w;

    float s = x.x + x.y + x.z + x.w;
#pragma unroll
    for (int off = 16; off; off >>= 1) s += __shfl_xor_sync(~0u, s, off);
    float mu = s * (1.0f / 128.0f);
    float d0 = x.x - mu, d1 = x.y - mu, d2 = x.z - mu, d3 = x.w - mu;
    float s2 = d0 * d0 + d1 * d1 + d2 * d2 + d3 * d3;
#pragma unroll
    for (int off = 16; off; off >>= 1) s2 += __shfl_xor_sync(~0u, s2, off);
    float rstd = rsqrtf(s2 * (1.0f / 128.0f) + 1e-5f);

    float y0 = d0 * rstd * gg.x + be.x;
    float y1 = d1 * rstd * gg.y + be.y;
    float y2 = d2 * rstd * gg.z + be.z;
    float y3 = d3 * rstd * gg.w + be.w;
    y0 = y0 / (1.0f + expf(-y0));
    y1 = y1 / (1.0f + expf(-y1));
    y2 = y2 / (1.0f + expf(-y2));
    y3 = y3 / (1.0f + expf(-y3));

    uint4 o;
    split_pair(y0, y1, o.x, o.y);
    split_pair(y2, y3, o.z, o.w);
    outp[(size_t)row * 32 + lane] = o;
}

// ---------------------------------------------------------------------------
// combine (final): sum partials + bias + LN + SiLU + FUSED residual GEMM.
// ---------------------------------------------------------------------------
template <int NSPLIT>
__global__ void __launch_bounds__(256) combine_final(
    const float* __restrict__ part, int M,
    const float* __restrict__ bias, const float* __restrict__ gamma,
    const float* __restrict__ beta, const float* __restrict__ ch,
    const float* __restrict__ Wres, const float* __restrict__ bres,
    float* __restrict__ out, int n_out)
{
    __shared__ float s_w[64 * 128];
    const int tid = threadIdx.x;
    const int lane = tid & 31;
    const int row = blockIdx.x * 8 + (tid >> 5);

    for (int i = tid; i < 2048; i += 256)
        ((float4*)s_w)[i] = ((const float4*)Wres)[i];
    __syncthreads();

    const int b2 = row / n_out;
    const int nn = row % n_out;

    const float* chrow = ch + ((size_t)b2 * 8192 + 4 * (size_t)nn) * 64;
    float4 racc = *(const float4*)(bres + lane * 4);
#pragma unroll 8
    for (int k = 0; k < 64; k++) {
        float a = __ldg(chrow + k);
        float4 w = *(const float4*)(s_w + k * 128 + lane * 4);
        racc.x += a * w.x; racc.y += a * w.y;
        racc.z += a * w.z; racc.w += a * w.w;
    }

    const float4* p4 = (const float4*)part;
    float4 x = p4[(size_t)row * 32 + lane];
#pragma unroll
    for (int s = 1; s < NSPLIT; s++) {
        float4 y = p4[((size_t)s * M + row) * 32 + lane];
        x.x += y.x; x.y += y.y; x.z += y.z; x.w += y.w;
    }
    float4 bb = *(const float4*)(bias + lane * 4);
    float4 gg = *(const float4*)(gamma + lane * 4);
    float4 be = *(const float4*)(beta + lane * 4);
    x.x += bb.x; x.y += bb.y; x.z += bb.z; x.w += bb.w;

    float s = x.x + x.y + x.z + x.w;
#pragma unroll
    for (int off = 16; off; off >>= 1) s += __shfl_xor_sync(~0u, s, off);
    float mu = s * (1.0f / 128.0f);
    float d0 = x.x - mu, d1 = x.y - mu, d2 = x.z - mu, d3 = x.w - mu;
    float s2 = d0 * d0 + d1 * d1 + d2 * d2 + d3 * d3;
#pragma unroll
    for (int off = 16; off; off >>= 1) s2 += __shfl_xor_sync(~0u, s2, off);
    float rstd = rsqrtf(s2 * (1.0f / 128.0f) + 1e-5f);

    float y0 = d0 * rstd * gg.x + be.x;
    float y1 = d1 * rstd * gg.y + be.y;
    float y2 = d2 * rstd * gg.z + be.z;
    float y3 = d3 * rstd * gg.w + be.w;
    float4 o4;
    o4.x = y0 / (1.0f + expf(-y0)) + racc.x;
    o4.y = y1 / (1.0f + expf(-y1)) + racc.y;
    o4.z = y2 / (1.0f + expf(-y2)) + racc.z;
    o4.w = y3 / (1.0f + expf(-y3)) + racc.w;

    ((float4*)out)[(size_t)row * 32 + lane] = o4;
}

// ---------------------------------------------------------------------------
extern "C" void kernel_launch(void* const* d_in, const int* in_sizes, int n_in,
                              void* d_out, int out_size)
{
    const float* pos  = (const float*)d_in[0];
    const float* ch   = (const float*)d_in[1];
    const float* W1   = (const float*)d_in[2];
    const float* b1   = (const float*)d_in[3];
    const float* Wres = (const float*)d_in[4];
    const float* bres = (const float*)d_in[5];
    const float* W2   = (const float*)d_in[6];
    const float* b2   = (const float*)d_in[7];
    const float* g1   = (const float*)d_in[8];
    const float* be1  = (const float*)d_in[9];
    const float* g2   = (const float*)d_in[10];
    const float* be2  = (const float*)d_in[11];
    float* out = (float*)d_out;

    int *knn1p, *knn2p;
    float *partp;
    uint4 *w1p, *w2p, *chp, *c1p;
    cudaGetSymbolAddress((void**)&knn1p, g_knn1);
    cudaGetSymbolAddress((void**)&knn2p, g_knn2);
    cudaGetSymbolAddress((void**)&partp, g_part);
    cudaGetSymbolAddress((void**)&w1p, g_W1p);
    cudaGetSymbolAddress((void**)&w2p, g_W2p);
    cudaGetSymbolAddress((void**)&chp, g_chp);
    cudaGetSymbolAddress((void**)&c1p, g_ch1p);

    // dynamic smem: 6 stages x (A 8448B + B 8192B) + 12 mbarriers = 99936 B
    constexpr int SMEM = 6 * (8 * 132 * 8 + 512 * 16) + 96;
    cudaFuncSetAttribute(gconv_mma<64, 4>,
                         cudaFuncAttributeMaxDynamicSharedMemorySize, SMEM);
    cudaFuncSetAttribute(gconv_mma<128, 8>,
                         cudaFuncAttributeMaxDynamicSharedMemorySize, SMEM);

    // fused prep: KNN (blocks 0..1535) + splits + poscopy (1536..2991)
    prep_kernel<<<2992, 256>>>(pos, knn1p, knn2p, W1, W2, ch, out);
    // conv1: split-K 4 -> partials -> combine (writes ch1 packed)
    gconv_mma<64, 4><<<dim3(64, 4), 256, SMEM>>>(
        (const uint2*)chp, knn1p, w1p, partp, 8192, 4096, 8192);
    combine_mid<4><<<1024, 256>>>(partp, 8192, b1, g1, be1, c1p);
    // conv2: split-K 8 -> partials -> combine (+fused residual, float out)
    gconv_mma<128, 8><<<dim3(32, 8), 256, SMEM>>>(
        (const uint2*)c1p, knn2p, w2p, partp, 4096, 2048, 4096);
    combine_final<8><<<512, 256>>>(
        partp, 4096, b2, g2, be2, ch, Wres, bres, out + 2 * 2048 * 3, 2048);
}

// round 15
// speedup vs baseline: 1.0394x; 1.0394x over previous
#include <cuda_runtime.h>
#include <cstdint>
#include <cstddef>
#include <math.h>

// ---------------------------------------------------------------------------
// Scratch (device globals -- no allocation allowed)
// ---------------------------------------------------------------------------
__device__ int   g_knn1[2 * 4096 * 16];
__device__ int   g_knn2[2 * 2048 * 16];
__device__ float g_part[4194304];          // split-K partials (16MB)
__device__ float g_res[524288];            // residual rows (2MB)
__device__ uint4 g_W1p[32768];             // W1 bf16 h/m fragment-permuted
__device__ uint4 g_W2p[65536];             // W2 bf16 h/m fragment-permuted
__device__ uint4 g_chp[262144];            // ch  packed bf16 h/m pairs (4MB)
__device__ uint4 g_ch1p[262144];           // ch1 packed bf16 h/m pairs (4MB)

// ---------------------------------------------------------------------------
// helpers
// ---------------------------------------------------------------------------
__device__ __forceinline__ unsigned int pack_bf16(float a, float b) {
    unsigned int r;
    asm("cvt.rn.bf16x2.f32 %0, %1, %2;" : "=r"(r) : "f"(b), "f"(a));
    return r;
}
__device__ __forceinline__ void split_pair(float v0, float v1,
                                           unsigned int& hp, unsigned int& mp) {
    hp = pack_bf16(v0, v1);
    float h0 = __uint_as_float(hp << 16);
    float h1 = __uint_as_float(hp & 0xffff0000u);
    mp = pack_bf16(v0 - h0, v1 - h1);
}
__device__ __forceinline__ void mma_bf16(float c[4], const unsigned int a[4],
                                         unsigned int b0, unsigned int b1) {
    asm("mma.sync.aligned.m16n8k16.row.col.f32.bf16.bf16.f32 "
        "{%0,%1,%2,%3}, {%4,%5,%6,%7}, {%8,%9}, {%0,%1,%2,%3};"
        : "+f"(c[0]), "+f"(c[1]), "+f"(c[2]), "+f"(c[3])
        : "r"(a[0]), "r"(a[1]), "r"(a[2]), "r"(a[3]), "r"(b0), "r"(b1));
}
__device__ __forceinline__ unsigned long long pack2(float x, float y) {
    unsigned long long r;
    asm("mov.b64 %0, {%1, %2};" : "=l"(r) : "f"(x), "f"(y));
    return r;
}
__device__ __forceinline__ unsigned long long add2(unsigned long long a,
                                                   unsigned long long b) {
    unsigned long long r;
    asm("add.rn.f32x2 %0, %1, %2;" : "=l"(r) : "l"(a), "l"(b));
    return r;
}
__device__ __forceinline__ unsigned long long mul2(unsigned long long a,
                                                   unsigned long long b) {
    unsigned long long r;
    asm("mul.rn.f32x2 %0, %1, %2;" : "=l"(r) : "l"(a), "l"(b));
    return r;
}
__device__ __forceinline__ void cp_async8(unsigned int dst, const void* src) {
    asm volatile("cp.async.ca.shared.global [%0], [%1], 8;"
                 :: "r"(dst), "l"(src));
}
__device__ __forceinline__ void cp_async16(unsigned int dst, const void* src) {
    asm volatile("cp.async.cg.shared.global [%0], [%1], 16;"
                 :: "r"(dst), "l"(src));
}

// ---------------------------------------------------------------------------
// prep: one kernel, block-range dispatch:
//  blocks [0,1024)    : KNN stage 1
//  blocks [1024,1536) : KNN stage 2
//  blocks [1536,2992) : W1/W2 bf16 fragment-permute, ch split, pos copy
//  blocks [2992,3504) : residual GEMM rows (res = bres + ch[b,4n,:] @ Wres)
// KNN: warp-per-center, negated-SoA smem tiles, packed f32x2 distance math
// (rounds exactly like scalar rn ops). Lanes 0..15 hold sorted top-16 u64
// keys ((dist_bits<<32)|idx); reproduces jax.lax.top_k(-d2) ordering exactly.
// ---------------------------------------------------------------------------
__global__ void __launch_bounds__(256) prep_kernel(
    const float* __restrict__ pos, int* __restrict__ knn1,
    int* __restrict__ knn2,
    const float* __restrict__ W1, const float* __restrict__ W2,
    const float* __restrict__ ch, const float* __restrict__ Wres,
    const float* __restrict__ bres, float* __restrict__ out)
{
    constexpr int TILE = 1024;
    __shared__ __align__(16) float sn[3 * TILE];   // -x @0, -y @1024, -z @2048

    const int tid = threadIdx.x;

    if (blockIdx.x >= 2992) {
        // ---------------- residual GEMM region ----------------
        const int lane = tid & 31;
        const int row = (blockIdx.x - 2992) * 8 + (tid >> 5);   // 0..4095
        const int b2 = row >> 11;
        const int nn = row & 2047;
        const float* chrow = ch + ((size_t)b2 * 8192 + 4 * (size_t)nn) * 64;
        float4 racc = *(const float4*)(bres + lane * 4);
#pragma unroll 8
        for (int k = 0; k < 64; k++) {
            float a = __ldg(chrow + k);
            float4 w = __ldg((const float4*)(Wres + k * 128) + lane);
            racc.x += a * w.x; racc.y += a * w.y;
            racc.z += a * w.z; racc.w += a * w.w;
        }
        *(float4*)(g_res + (size_t)row * 128 + lane * 4) = racc;
        return;
    }

    if (blockIdx.x >= 1536) {
        int i = (blockIdx.x - 1536) * 256 + tid;
        if (i < 32768) {                               // W1p
            int p = i >> 9, n = (i >> 2) & 127, t = i & 3;
            int k0 = 16 * p + 2 * t;
            float v0 = __ldg(W1 + n * 1024 + k0);
            float v1 = __ldg(W1 + n * 1024 + k0 + 1);
            float v2 = __ldg(W1 + n * 1024 + k0 + 8);
            float v3 = __ldg(W1 + n * 1024 + k0 + 9);
            uint4 o;
            split_pair(v0, v1, o.x, o.z);
            split_pair(v2, v3, o.y, o.w);
            g_W1p[i] = o;
        } else if (i < 98304) {                        // W2p
            int j = i - 32768;
            int p = j >> 9, n = (j >> 2) & 127, t = j & 3;
            int k0 = 16 * p + 2 * t;
            float v0 = __ldg(W2 + n * 2048 + k0);
            float v1 = __ldg(W2 + n * 2048 + k0 + 1);
            float v2 = __ldg(W2 + n * 2048 + k0 + 8);
            float v3 = __ldg(W2 + n * 2048 + k0 + 9);
            uint4 o;
            split_pair(v0, v1, o.x, o.z);
            split_pair(v2, v3, o.y, o.w);
            g_W2p[j] = o;
        } else if (i < 360448) {                       // chp (4 floats/thr)
            int j = i - 98304;
            float4 v = __ldg((const float4*)ch + j);
            uint4 o;
            split_pair(v.x, v.y, o.x, o.y);
            split_pair(v.z, v.w, o.z, o.w);
            g_chp[j] = o;
        } else if (i < 372736) {                       // pos copy
            int j = i - 360448;
            int b = j / 6144;
            int rem = j - b * 6144;
            int n = rem / 3;
            int d = rem - n * 3;
            out[j] = pos[((size_t)b * 8192 + 4 * n) * 3 + d];
        }
        return;
    }

    // -------------------- KNN region (R9-proven formulation) ----------------
    const int warp = tid >> 5;
    const int lane = tid & 31;

    int pstride, n_in, n_out, center;
    int* outp;
    if (blockIdx.x < 1024) {
        pstride = 1; n_in = 8192; n_out = 4096; outp = knn1;
        center = blockIdx.x * 8 + warp;
    } else {
        pstride = 2; n_in = 4096; n_out = 2048; outp = knn2;
        center = (blockIdx.x - 1024) * 8 + warp;
    }
    const int b = center / n_out;
    const int n = center % n_out;

    const float* posb = pos + (size_t)b * 8192 * 3;
    const float cx = posb[(size_t)(n * 2 * pstride) * 3 + 0];
    const float cy = posb[(size_t)(n * 2 * pstride) * 3 + 1];
    const float cz = posb[(size_t)(n * 2 * pstride) * 3 + 2];
    const unsigned long long cxx = pack2(cx, cx);
    const unsigned long long cyy = pack2(cy, cy);
    const unsigned long long czz = pack2(cz, cz);

    unsigned long long lkey   = 0x7F800000FFFFFFFFull;
    unsigned long long thresh = 0x7F800000FFFFFFFFull;
    float tf = __int_as_float(0x7F800000);

    const int nTiles = n_in / TILE;
    float v[12];

#pragma unroll
    for (int k = 0; k < 4; k++) {
        int p = k * 256 + tid;
#pragma unroll
        for (int d = 0; d < 3; d++)
            v[3 * k + d] = __ldg(posb + (size_t)p * pstride * 3 + d);
    }

    for (int t = 0; t < nTiles; t++) {
#pragma unroll
        for (int k = 0; k < 4; k++) {
            int p = k * 256 + tid;
            sn[p]        = -v[3 * k];
            sn[p + 1024] = -v[3 * k + 1];
            sn[p + 2048] = -v[3 * k + 2];
        }
        __syncthreads();
        if (t + 1 < nTiles) {
            const int base = (t + 1) * TILE;
#pragma unroll
            for (int k = 0; k < 4; k++) {
                int p = base + k * 256 + tid;
#pragma unroll
                for (int d = 0; d < 3; d++)
                    v[3 * k + d] = __ldg(posb + (size_t)p * pstride * 3 + d);
            }
        }

        const int jbase = t * TILE;
#pragma unroll 4
        for (int it = 0; it < 16; ++it) {
            const int j = it * 64 + 2 * lane;
            unsigned long long nx = *(const unsigned long long*)(sn + j);
            unsigned long long ny = *(const unsigned long long*)(sn + 1024 + j);
            unsigned long long nz = *(const unsigned long long*)(sn + 2048 + j);
            unsigned long long ax = add2(cxx, nx);
            unsigned long long ay = add2(cyy, ny);
            unsigned long long az = add2(czz, nz);
            unsigned long long dp =
                add2(add2(mul2(ax, ax), mul2(ay, ay)), mul2(az, az));
            float d0, d1;
            asm("mov.b64 {%0, %1}, %2;" : "=f"(d0), "=f"(d1) : "l"(dp));
#pragma unroll
            for (int h = 0; h < 2; h++) {
                float dv = h ? d1 : d0;
                unsigned mask = __ballot_sync(0xffffffffu, dv <= tf);
                while (mask) {
                    const int src = __ffs(mask) - 1;
                    mask &= mask - 1;
                    float cd = __shfl_sync(0xffffffffu, dv, src);
                    unsigned idx = (unsigned)(jbase + it * 64 + 2 * src + h);
                    unsigned long long ck =
                        ((unsigned long long)__float_as_uint(cd) << 32) | idx;
                    if (ck < thresh) {
                        unsigned long long up =
                            __shfl_up_sync(0xffffffffu, lkey, 1);
                        bool keep = (lkey < ck);
                        unsigned long long ins =
                            (lane == 0 || up < ck) ? ck : up;
                        lkey = keep ? lkey : ins;
                        thresh = __shfl_sync(0xffffffffu, lkey, 15);
                        tf = __uint_as_float((unsigned)(thresh >> 32));
                    }
                }
            }
        }
        __syncthreads();
    }

    if (lane < 16)
        outp[(size_t)center * 16 + lane] =
            (int)(unsigned)(lkey & 0xffffffffull);
}

// ---------------------------------------------------------------------------
// Gathered-conv GEMM, 3xBF16 (h+m split) m16n8k16 tensor cores, 4-stage
// cp.async ring (BK=16). knn indices preloaded & packed in a register
// (13 bits each) -- no per-iter dependent LDG in the fill path.
// ---------------------------------------------------------------------------
template <int CIN, int NSPLIT>
__global__ void __launch_bounds__(256, 2)
gconv_mma(const uint2* __restrict__ chp, const int* __restrict__ knn,
          const uint4* __restrict__ Wp, float* __restrict__ part,
          int n_in, int n_out, int Mtot)
{
    constexpr int BM = 128, BN = 128, BK = 16, S2 = 132, STAGES = 4;
    constexpr int APLANE = 8 * S2;           // 8 kpairs x 132 rows (uint2)
    constexpr int BPLANE = 512;              // uint4 per k16 panel
    constexpr int NPB = 16 / NSPLIT;
    constexpr int ITERS = NPB * CIN / BK;
    constexpr int CIN2 = CIN / 2;            // uint2 per row
    extern __shared__ __align__(16) unsigned char dynraw[];
    uint2* As2 = (uint2*)dynraw;                           // STAGES*APLANE
    uint4* Bs4 = (uint4*)(dynraw + STAGES * APLANE * 8);   // STAGES*BPLANE

    const int tid = threadIdx.x;
    const int split = blockIdx.y;
    const int m_base = blockIdx.x * BM;
    const int b = m_base / n_out;
    const int warp = tid >> 5, lane = tid & 31;
    const int g = lane >> 2, t = lane & 3;
    const int wm = (warp & 3) * 32, wn = (warp >> 2) * 64;

    const int arow = tid >> 1;
    const int ahalf = (tid & 1) * 4;         // kpair half (0 or 4)
    const uint2* chb = chp + (size_t)b * n_in * CIN2;
    const int kpan0 = (split * NPB * CIN) >> 4;   // 16-wide k panels

    // preload this row's neighbor indices for this split, pack 13b each
    unsigned long long jpack;
    {
        const int* base = knn + ((size_t)(m_base + arow) * 16) + split * NPB;
        if (NPB == 4) {
            int4 j4 = *(const int4*)base;
            jpack = (unsigned long long)(unsigned)j4.x
                  | ((unsigned long long)(unsigned)j4.y << 13)
                  | ((unsigned long long)(unsigned)j4.z << 26)
                  | ((unsigned long long)(unsigned)j4.w << 39);
        } else {
            int2 j2 = *(const int2*)base;
            jpack = (unsigned long long)(unsigned)j2.x
                  | ((unsigned long long)(unsigned)j2.y << 13);
        }
    }

    const unsigned int abase =
        (unsigned int)__cvta_generic_to_shared(As2) + (ahalf * S2 + arow) * 8;
    const unsigned int bbase =
        (unsigned int)__cvta_generic_to_shared(Bs4) + tid * 32;

    float acc[2][8][4];
#pragma unroll
    for (int i = 0; i < 2; i++)
#pragma unroll
        for (int j = 0; j < 8; j++)
#pragma unroll
            for (int k = 0; k < 4; k++) acc[i][j][k] = 0.0f;

    auto issue = [&](int it, int buf) {
        const int kn = (it * BK) / CIN;      // local neighbor in split
        const int j = (int)((jpack >> (kn * 13)) & 8191);
        const int c0 = ((it * BK) % CIN) >> 1;
        const uint2* srcA = chb + (size_t)j * CIN2 + c0 + ahalf;
        const unsigned int dA = abase + buf * (APLANE * 8);
#pragma unroll
        for (int i = 0; i < 4; i++) cp_async8(dA + i * (S2 * 8), srcA + i);
        const uint4* srcB = Wp + ((size_t)(kpan0 + it) << 9) + tid * 2;
        const unsigned int dB = bbase + buf * (BPLANE * 16);
#pragma unroll
        for (int q = 0; q < 2; q++) cp_async16(dB + q * 16, srcB + q);
    };

    issue(0, 0); asm volatile("cp.async.commit_group;");
    issue(1, 1); asm volatile("cp.async.commit_group;");
    issue(2, 2); asm volatile("cp.async.commit_group;");

    for (int it = 0; it < ITERS; ++it) {
        asm volatile("cp.async.wait_group 2;");
        __syncthreads();
        if (it + 3 < ITERS) issue(it + 3, (it + 3) & 3);
        asm volatile("cp.async.commit_group;");

        const uint2* As = As2 + (it & 3) * APLANE;
        const uint4* Bs = Bs4 + (it & 3) * BPLANE;

        unsigned int Ah[2][4], Am[2][4];
#pragma unroll
        for (int mt = 0; mt < 2; mt++) {
            const int r0 = wm + mt * 16 + g;
            uint2 a0 = As[t * S2 + r0];
            uint2 a1 = As[t * S2 + r0 + 8];
            uint2 a2 = As[(t + 4) * S2 + r0];
            uint2 a3 = As[(t + 4) * S2 + r0 + 8];
            Ah[mt][0] = a0.x; Am[mt][0] = a0.y;
            Ah[mt][1] = a1.x; Am[mt][1] = a1.y;
            Ah[mt][2] = a2.x; Am[mt][2] = a2.y;
            Ah[mt][3] = a3.x; Am[mt][3] = a3.y;
        }
#pragma unroll
        for (int nt = 0; nt < 8; nt++) {
            uint4 w = Bs[(wn + nt * 8 + g) * 4 + t];   // {bh0,bh1,bm0,bm1}
#pragma unroll
            for (int mt = 0; mt < 2; mt++) {
                mma_bf16(acc[mt][nt], Ah[mt], w.x, w.y);
                mma_bf16(acc[mt][nt], Ah[mt], w.z, w.w);
                mma_bf16(acc[mt][nt], Am[mt], w.x, w.y);
            }
        }
    }

    float* dst = part + ((size_t)split * Mtot + m_base) * BN;
#pragma unroll
    for (int mt = 0; mt < 2; mt++)
#pragma unroll
        for (int nt = 0; nt < 8; nt++) {
            const int r = wm + mt * 16 + g;
            const int c = wn + nt * 8 + 2 * t;
            *(float2*)(dst + (size_t)r * BN + c) =
                make_float2(acc[mt][nt][0], acc[mt][nt][1]);
            *(float2*)(dst + (size_t)(r + 8) * BN + c) =
                make_float2(acc[mt][nt][2], acc[mt][nt][3]);
        }
}

// ---------------------------------------------------------------------------
// combine (mid): sum partials + bias + LN + SiLU -> packed bf16 h/m pairs
// ---------------------------------------------------------------------------
template <int NSPLIT>
__global__ void __launch_bounds__(256) combine_mid(
    const float* __restrict__ part, int M,
    const float* __restrict__ bias, const float* __restrict__ gamma,
    const float* __restrict__ beta, uint4* __restrict__ outp)
{
    const int lane = threadIdx.x & 31;
    const int row = blockIdx.x * 8 + (threadIdx.x >> 5);

    const float4* p4 = (const float4*)part;
    float4 x = p4[(size_t)row * 32 + lane];
#pragma unroll
    for (int s = 1; s < NSPLIT; s++) {
        float4 y = p4[((size_t)s * M + row) * 32 + lane];
        x.x += y.x; x.y += y.y; x.z += y.z; x.w += y.w;
    }
    float4 bb = *(const float4*)(bias + lane * 4);
    float4 gg = *(const float4*)(gamma + lane * 4);
    float4 be = *(const float4*)(beta + lane * 4);
    x.x += bb.x; x.y += bb.y; x.z += bb.z; x.w += bb.w;

    float s = x.x + x.y + x.z + x.w;
#pragma unroll
    for (int off = 16; off; off >>= 1) s += __shfl_xor_sync(~0u, s, off);
    float mu = s * (1.0f / 128.0f);
    float d0 = x.x - mu, d1 = x.y - mu, d2 = x.z - mu, d3 = x.w - mu;
    float s2 = d0 * d0 + d1 * d1 + d2 * d2 + d3 * d3;
#pragma unroll
    for (int off = 16; off; off >>= 1) s2 += __shfl_xor_sync(~0u, s2, off);
    float rstd = rsqrtf(s2 * (1.0f / 128.0f) + 1e-5f);

    float y0 = d0 * rstd * gg.x + be.x;
    float y1 = d1 * rstd * gg.y + be.y;
    float y2 = d2 * rstd * gg.z + be.z;
    float y3 = d3 * rstd * gg.w + be.w;
    y0 = y0 / (1.0f + expf(-y0));
    y1 = y1 / (1.0f + expf(-y1));
    y2 = y2 / (1.0f + expf(-y2));
    y3 = y3 / (1.0f + expf(-y3));

    uint4 o;
    split_pair(y0, y1, o.x, o.y);
    split_pair(y2, y3, o.z, o.w);
    outp[(size_t)row * 32 + lane] = o;
}

// ---------------------------------------------------------------------------
// combine (final): sum partials + bias + LN + SiLU + precomputed residual add
// ---------------------------------------------------------------------------
template <int NSPLIT>
__global__ void __launch_bounds__(256) combine_final(
    const float* __restrict__ part, int M,
    const float* __restrict__ bias, const float* __restrict__ gamma,
    const float* __restrict__ beta, const float* __restrict__ res,
    float* __restrict__ out, int n_out)
{
    const int lane = threadIdx.x & 31;
    const int row = blockIdx.x * 8 + (threadIdx.x >> 5);

    const float4* p4 = (const float4*)part;
    float4 x = p4[(size_t)row * 32 + lane];
#pragma unroll
    for (int s = 1; s < NSPLIT; s++) {
        float4 y = p4[((size_t)s * M + row) * 32 + lane];
        x.x += y.x; x.y += y.y; x.z += y.z; x.w += y.w;
    }
    float4 bb = *(const float4*)(bias + lane * 4);
    float4 gg = *(const float4*)(gamma + lane * 4);
    float4 be = *(const float4*)(beta + lane * 4);
    x.x += bb.x; x.y += bb.y; x.z += bb.z; x.w += bb.w;

    float s = x.x + x.y + x.z + x.w;
#pragma unroll
    for (int off = 16; off; off >>= 1) s += __shfl_xor_sync(~0u, s, off);
    float mu = s * (1.0f / 128.0f);
    float d0 = x.x - mu, d1 = x.y - mu, d2 = x.z - mu, d3 = x.w - mu;
    float s2 = d0 * d0 + d1 * d1 + d2 * d2 + d3 * d3;
#pragma unroll
    for (int off = 16; off; off >>= 1) s2 += __shfl_xor_sync(~0u, s2, off);
    float rstd = rsqrtf(s2 * (1.0f / 128.0f) + 1e-5f);

    float y0 = d0 * rstd * gg.x + be.x;
    float y1 = d1 * rstd * gg.y + be.y;
    float y2 = d2 * rstd * gg.z + be.z;
    float y3 = d3 * rstd * gg.w + be.w;

    const float4 rr = *(const float4*)(res + (size_t)row * 128 + lane * 4);
    float4 o4;
    o4.x = y0 / (1.0f + expf(-y0)) + rr.x;
    o4.y = y1 / (1.0f + expf(-y1)) + rr.y;
    o4.z = y2 / (1.0f + expf(-y2)) + rr.z;
    o4.w = y3 / (1.0f + expf(-y3)) + rr.w;

    ((float4*)out)[(size_t)row * 32 + lane] = o4;
}

// ---------------------------------------------------------------------------
extern "C" void kernel_launch(void* const* d_in, const int* in_sizes, int n_in,
                              void* d_out, int out_size)
{
    const float* pos  = (const float*)d_in[0];
    const float* ch   = (const float*)d_in[1];
    const float* W1   = (const float*)d_in[2];
    const float* b1   = (const float*)d_in[3];
    const float* Wres = (const float*)d_in[4];
    const float* bres = (const float*)d_in[5];
    const float* W2   = (const float*)d_in[6];
    const float* b2   = (const float*)d_in[7];
    const float* g1   = (const float*)d_in[8];
    const float* be1  = (const float*)d_in[9];
    const float* g2   = (const float*)d_in[10];
    const float* be2  = (const float*)d_in[11];
    float* out = (float*)d_out;

    int *knn1p, *knn2p;
    float *partp, *resp;
    uint4 *w1p, *w2p, *chp, *c1p;
    cudaGetSymbolAddress((void**)&knn1p, g_knn1);
    cudaGetSymbolAddress((void**)&knn2p, g_knn2);
    cudaGetSymbolAddress((void**)&partp, g_part);
    cudaGetSymbolAddress((void**)&resp, g_res);
    cudaGetSymbolAddress((void**)&w1p, g_W1p);
    cudaGetSymbolAddress((void**)&w2p, g_W2p);
    cudaGetSymbolAddress((void**)&chp, g_chp);
    cudaGetSymbolAddress((void**)&c1p, g_ch1p);

    // dynamic smem: 4 stages x (A 8448B + B 8192B) = 66560 B
    constexpr int SMEM = 4 * (8 * 132 * 8 + 512 * 16);
    cudaFuncSetAttribute(gconv_mma<64, 4>,
                         cudaFuncAttributeMaxDynamicSharedMemorySize, SMEM);
    cudaFuncSetAttribute(gconv_mma<128, 8>,
                         cudaFuncAttributeMaxDynamicSharedMemorySize, SMEM);

    // fused prep: KNN (0..1535) + splits/poscopy (1536..2991)
    //           + residual GEMM (2992..3503)
    prep_kernel<<<3504, 256>>>(pos, knn1p, knn2p, W1, W2, ch, Wres, bres, out);
    // conv1: split-K 4 -> partials -> combine (writes ch1 packed)
    gconv_mma<64, 4><<<dim3(64, 4), 256, SMEM>>>(
        (const uint2*)chp, knn1p, w1p, partp, 8192, 4096, 8192);
    combine_mid<4><<<1024, 256>>>(partp, 8192, b1, g1, be1, c1p);
    // conv2: split-K 8 -> partials -> combine (+precomputed residual)
    gconv_mma<128, 8><<<dim3(32, 8), 256, SMEM>>>(
        (const uint2*)c1p, knn2p, w2p, partp, 4096, 2048, 4096);
    combine_final<8><<<512, 256>>>(
        partp, 4096, b2, g2, be2, resp, out + 2 * 2048 * 3, 2048);
}